// round 1
// baseline (speedup 1.0000x reference)
#include <cuda_runtime.h>
#include <cuda_bf16.h>
#include <cstdint>

typedef unsigned long long ull;

// ---------------- scratch (device globals: allocation-free) ----------------
__device__ float g_xw[(size_t)64 * 1024 * 1536];   // 402 MB input projections
__device__ float g_h0[64 * 512];
__device__ float g_h1[64 * 512];
__device__ unsigned g_arrive = 0;
__device__ unsigned g_release = 0;

// ---------------- f32x2 helpers ----------------
__device__ __forceinline__ void fma2(ull& d, ull a, ull b) {
    asm("fma.rn.f32x2 %0, %1, %2, %0;" : "+l"(d) : "l"(a), "l"(b));
}
__device__ __forceinline__ ull splat2(float x) {
    ull r; asm("mov.b64 %0, {%1, %1};" : "=l"(r) : "f"(x)); return r;
}
__device__ __forceinline__ void f4_to_u2(float4 v, ull& a, ull& b) {
    asm("mov.b64 %0, {%1, %2};" : "=l"(a) : "f"(v.x), "f"(v.y));
    asm("mov.b64 %0, {%1, %2};" : "=l"(b) : "f"(v.z), "f"(v.w));
}
__device__ __forceinline__ float2 unpk(ull v) {
    float2 r; asm("mov.b64 {%0, %1}, %2;" : "=f"(r.x), "=f"(r.y) : "l"(v)); return r;
}

__device__ __forceinline__ float sigf(float x) {
    return __fdividef(1.0f, 1.0f + __expf(-x));
}
__device__ __forceinline__ float tanh_acc(float x) {
    float ax = fabsf(x);
    float e = __expf(-2.0f * ax);
    float r = __fdividef(1.0f - e, 1.0f + e);
    return copysignf(r, x);
}

// ============================================================================
// Phase 1: xw = x @ W + b_in    (M=65536, K=512, N=1536), f32x2 SGEMM
// ============================================================================
#define P1_BM 128
#define P1_BN 64
#define P1_BK 16

__global__ void __launch_bounds__(256) gemm_xw_kernel(
    const float* __restrict__ A,     // [65536, 512]
    const float* __restrict__ W,     // [512, 1536]
    const float* __restrict__ bias,  // [2, 1536] (row 0 = b_in)
    float* __restrict__ C)           // [65536, 1536]
{
    __shared__ float As[P1_BK * (P1_BM + 4)];   // transposed: As[k][m]
    __shared__ float Bs[P1_BK * P1_BN];         // Bs[k][n]

    const int tid = threadIdx.x;
    const int tx = tid & 15;          // 16 n-groups
    const int ty = tid >> 4;          // 16 m-groups
    const int bm = blockIdx.y * P1_BM;
    const int bn = blockIdx.x * P1_BN;

    ull acc[8][2];
#pragma unroll
    for (int m = 0; m < 8; m++) { acc[m][0] = 0ull; acc[m][1] = 0ull; }

    for (int kk = 0; kk < 512; kk += P1_BK) {
        // load A tile 128x16 (512 float4 slots, 2 per thread), transpose into As
#pragma unroll
        for (int i = 0; i < 2; i++) {
            int s = tid + i * 256;
            int m = s >> 2;
            int kq = (s & 3) << 2;
            float4 v = *(const float4*)(A + (size_t)(bm + m) * 512 + kk + kq);
            As[(kq + 0) * (P1_BM + 4) + m] = v.x;
            As[(kq + 1) * (P1_BM + 4) + m] = v.y;
            As[(kq + 2) * (P1_BM + 4) + m] = v.z;
            As[(kq + 3) * (P1_BM + 4) + m] = v.w;
        }
        // load B tile 16x64 (256 float4 slots, 1 per thread)
        {
            int k = tid >> 4;
            int nq = (tid & 15) << 2;
            float4 v = *(const float4*)(W + (size_t)(kk + k) * 1536 + bn + nq);
            *(float4*)(Bs + k * P1_BN + nq) = v;
        }
        __syncthreads();

#pragma unroll
        for (int k = 0; k < P1_BK; k++) {
            float4 a0 = *(const float4*)(As + k * (P1_BM + 4) + ty * 8);
            float4 a1 = *(const float4*)(As + k * (P1_BM + 4) + ty * 8 + 4);
            float4 b4 = *(const float4*)(Bs + k * P1_BN + tx * 4);
            ull b01, b23;
            f4_to_u2(b4, b01, b23);
            float am[8] = {a0.x, a0.y, a0.z, a0.w, a1.x, a1.y, a1.z, a1.w};
#pragma unroll
            for (int m = 0; m < 8; m++) {
                ull as = splat2(am[m]);
                fma2(acc[m][0], as, b01);
                fma2(acc[m][1], as, b23);
            }
        }
        __syncthreads();
    }

    const int n0 = bn + tx * 4;
    float4 bi = *(const float4*)(bias + n0);
#pragma unroll
    for (int m = 0; m < 8; m++) {
        float2 p0 = unpk(acc[m][0]);
        float2 p1 = unpk(acc[m][1]);
        float4 o;
        o.x = p0.x + bi.x; o.y = p0.y + bi.y;
        o.z = p1.x + bi.z; o.w = p1.y + bi.w;
        *(float4*)(C + (size_t)(bm + ty * 8 + m) * 1536 + n0) = o;
    }
}

// ============================================================================
// Phase 2: persistent sequential GRU recurrence
//   128 blocks (one per SM), 256 threads, grid barrier per timestep.
//   Block owns units [u0, u0+4). R slice (12 cols) resident in smem.
//   GEMM: thread = (batch b, k-slice ks); 12 f32x2 accumulators (even/odd k).
// ============================================================================
#define NB 128
#define HS_STRIDE 516
#define RS_STRIDE 520
// smem layout in floats
#define OFF_HS   0                    // 64*516       = 33024
#define OFF_RS   33024                // 12*520       = 6240
#define OFF_RED  39264                // 64*4*12      = 3072
#define OFF_XWS  42336                // 64*3*4       = 768
#define OFF_BRS  43104                // 16
#define OFF_HNEW 43120                // 256
#define SM2_FLOATS 43376
#define SM2_BYTES (SM2_FLOATS * 4)

__device__ __forceinline__ void grid_barrier(int t) {
    __threadfence();
    __syncthreads();
    if (threadIdx.x == 0) {
        unsigned target = (unsigned)((t & 1) ^ 1);
        unsigned old = atomicAdd(&g_arrive, 1u);
        if (old == NB - 1) {
            g_arrive = 0;
            __threadfence();
            atomicExch(&g_release, target);
        } else {
            while (*((volatile unsigned*)&g_release) != target) {}
        }
    }
    __syncthreads();
}

__global__ void __launch_bounds__(256, 1) gru_seq_kernel(
    const float* __restrict__ xw,    // [65536, 1536]  (b*1024+t major)
    const float* __restrict__ rk,    // [512, 1536]
    const float* __restrict__ bias,  // [2, 1536] (row 1 = b_rec)
    float* __restrict__ out,         // [64, 1024, 512]
    float* __restrict__ h0buf,
    float* __restrict__ h1buf)
{
    extern __shared__ float sm[];
    float* hs   = sm + OFF_HS;
    float* Rs   = sm + OFF_RS;
    float* red  = sm + OFF_RED;
    float* xws  = sm + OFF_XWS;
    float* brs  = sm + OFF_BRS;
    float* hnew = sm + OFF_HNEW;

    const int tid = threadIdx.x;
    const int u0 = blockIdx.x * 4;

    // stage R slice: col c = j*3+g maps to global col g*512 + u0 + j
    for (int idx = tid; idx < 12 * 512; idx += 256) {
        int c = idx >> 9, k = idx & 511;
        int jj = c / 3, g = c - jj * 3;
        Rs[c * RS_STRIDE + k] = rk[(size_t)k * 1536 + g * 512 + u0 + jj];
    }
    if (tid < 12) {
        int jj = tid / 3, g = tid - jj * 3;
        brs[tid] = bias[1536 + g * 512 + u0 + jj];
    }
    __syncthreads();

    const int b = tid & 63;
    const int ks = tid >> 6;   // k-slice in GEMM; unit index j in epilogue
    const int j = ks;

    for (int t = 0; t < 1024; t++) {
        const float* hin  = (t & 1) ? h1buf : h0buf;
        float*       hout = (t & 1) ? h0buf : h1buf;

        // ---- stage h (L2-coherent path; L1 bypass) ----
        for (int i = tid; i < 8192; i += 256) {
            int bb = i >> 7;
            int k4 = (i & 127) << 2;
            float4 v = __ldcg((const float4*)(hin + bb * 512 + k4));
            *(float4*)(hs + bb * HS_STRIDE + k4) = v;
        }
        // ---- stage xw slice for this timestep ----
        if (tid < 192) {
            int bb = tid & 63, g = tid >> 6;
            float4 v = *(const float4*)(xw + (size_t)(bb * 1024 + t) * 1536 + g * 512 + u0);
            *(float4*)(xws + (bb * 3 + g) * 4) = v;
        }
        __syncthreads();

        // ---- GEMM partial: 12 cols x 128-k slice ----
        ull acc[12];
#pragma unroll
        for (int c = 0; c < 12; c++) acc[c] = 0ull;
        const float* hp = hs + b * HS_STRIDE + ks * 128;
        const float* rp = Rs + ks * 128;
        for (int kk = 0; kk < 128; kk += 4) {
            float4 h4 = *(const float4*)(hp + kk);
            ull h01, h23;
            f4_to_u2(h4, h01, h23);
#pragma unroll
            for (int c = 0; c < 12; c++) {
                float4 r4 = *(const float4*)(rp + c * RS_STRIDE + kk);
                ull r01, r23;
                f4_to_u2(r4, r01, r23);
                fma2(acc[c], h01, r01);
                fma2(acc[c], h23, r23);
            }
        }
        {
            float* rb = red + (b * 4 + ks) * 12;
#pragma unroll
            for (int c = 0; c < 12; c++) {
                float2 p = unpk(acc[c]);
                rb[c] = p.x + p.y;
            }
        }
        __syncthreads();

        // ---- gate math: thread = (b, unit j) ----
        float rz = brs[j * 3 + 0];
        float rr = brs[j * 3 + 1];
        float rh = brs[j * 3 + 2];
#pragma unroll
        for (int s = 0; s < 4; s++) {
            const float* q = red + (b * 4 + s) * 12 + j * 3;
            rz += q[0]; rr += q[1]; rh += q[2];
        }
        float xz = xws[(b * 3 + 0) * 4 + j];
        float xr = xws[(b * 3 + 1) * 4 + j];
        float xh = xws[(b * 3 + 2) * 4 + j];
        float hprev = hs[b * HS_STRIDE + u0 + j];

        float z  = sigf(xz + rz);
        float r  = sigf(xr + rr);
        float hh = tanh_acc(xh + r * rh);
        float hn = z * hprev + (1.0f - z) * hh;

        hnew[b * 4 + j] = hn;
        __syncthreads();

        if (tid < 64) {
            float4 v = *(float4*)(hnew + tid * 4);
            __stcg((float4*)(hout + tid * 512 + u0), v);
            *(float4*)(out + (size_t)tid * 524288 + (size_t)t * 512 + u0) = v;
        }

        grid_barrier(t);
    }
}

// ============================================================================
extern "C" void kernel_launch(void* const* d_in, const int* in_sizes, int n_in,
                              void* d_out, int out_size) {
    const float* x    = (const float*)d_in[0];   // [64,1024,512]
    const float* W    = (const float*)d_in[1];   // [512,1536]
    const float* R    = (const float*)d_in[2];   // [512,1536]
    const float* bias = (const float*)d_in[3];   // [2,1536]
    float* out = (float*)d_out;

    float *xw_ptr, *h0_ptr, *h1_ptr;
    cudaGetSymbolAddress((void**)&xw_ptr, g_xw);
    cudaGetSymbolAddress((void**)&h0_ptr, g_h0);
    cudaGetSymbolAddress((void**)&h1_ptr, g_h1);

    // h0 = zeros (initial state)
    cudaMemsetAsync(h0_ptr, 0, 64 * 512 * sizeof(float));

    dim3 g1(1536 / P1_BN, 65536 / P1_BM);
    gemm_xw_kernel<<<g1, 256>>>(x, W, bias, xw_ptr);

    cudaFuncSetAttribute(gru_seq_kernel,
                         cudaFuncAttributeMaxDynamicSharedMemorySize, SM2_BYTES);
    gru_seq_kernel<<<NB, 256, SM2_BYTES>>>(xw_ptr, R, bias, out, h0_ptr, h1_ptr);
}

// round 2
// speedup vs baseline: 2.0779x; 2.0779x over previous
#include <cuda_runtime.h>
#include <cuda_bf16.h>
#include <cstdint>

typedef unsigned long long ull;

// ---------------- scratch (device globals: allocation-free) ----------------
__device__ float g_xw[(size_t)64 * 1024 * 1536];   // 402 MB input projections
__device__ float g_h0[64 * 512];
__device__ float g_h1[64 * 512];
__device__ unsigned g_ctr[8 * 32];                 // per-batch-group counters, 128B apart

// ---------------- f32x2 helpers ----------------
__device__ __forceinline__ void fma2(ull& d, ull a, ull b) {
    asm("fma.rn.f32x2 %0, %1, %2, %0;" : "+l"(d) : "l"(a), "l"(b));
}
__device__ __forceinline__ ull splat2(float x) {
    ull r; asm("mov.b64 %0, {%1, %1};" : "=l"(r) : "f"(x)); return r;
}
__device__ __forceinline__ ull pack2(float x, float y) {
    ull r; asm("mov.b64 %0, {%1, %2};" : "=l"(r) : "f"(x), "f"(y)); return r;
}
__device__ __forceinline__ void f4_to_u2(float4 v, ull& a, ull& b) {
    asm("mov.b64 %0, {%1, %2};" : "=l"(a) : "f"(v.x), "f"(v.y));
    asm("mov.b64 %0, {%1, %2};" : "=l"(b) : "f"(v.z), "f"(v.w));
}
__device__ __forceinline__ float2 unpk(ull v) {
    float2 r; asm("mov.b64 {%0, %1}, %2;" : "=f"(r.x), "=f"(r.y) : "l"(v)); return r;
}

__device__ __forceinline__ float sigf(float x) {
    return __fdividef(1.0f, 1.0f + __expf(-x));
}
__device__ __forceinline__ float tanh_acc(float x) {
    float ax = fabsf(x);
    float e = __expf(-2.0f * ax);
    float r = __fdividef(1.0f - e, 1.0f + e);
    return copysignf(r, x);
}

// ============================================================================
// Phase 1: xw = x @ W + b_in    (M=65536, K=512, N=1536), f32x2 SGEMM
//   128x256 tile, 256 threads, 8m x 16n microtile (4 groups of 4 cols).
// ============================================================================
#define P1_BM 128
#define P1_BN 256
#define P1_BK 16

__global__ void __launch_bounds__(256, 1) gemm_xw_kernel(
    const float* __restrict__ A,     // [65536, 512]
    const float* __restrict__ W,     // [512, 1536]
    const float* __restrict__ bias,  // [2, 1536] (row 0 = b_in)
    float* __restrict__ C)           // [65536, 1536]
{
    __shared__ float As[P1_BK * (P1_BM + 4)];   // transposed: As[k][m]
    __shared__ float Bs[P1_BK * P1_BN];         // Bs[k][n]

    const int tid = threadIdx.x;
    const int tx = tid & 15;          // 16 n-thread-cols (4 floats each, x4 groups)
    const int ty = tid >> 4;          // 16 m-groups (8 rows each)
    const int bm = blockIdx.y * P1_BM;
    const int bn = blockIdx.x * P1_BN;

    ull acc[8][8];
#pragma unroll
    for (int m = 0; m < 8; m++)
#pragma unroll
        for (int g = 0; g < 8; g++) acc[m][g] = 0ull;

    for (int kk = 0; kk < 512; kk += P1_BK) {
        // A tile 128x16 (512 float4 slots, 2 per thread), transpose into As
#pragma unroll
        for (int i = 0; i < 2; i++) {
            int s = tid + i * 256;
            int m = s >> 2;
            int kq = (s & 3) << 2;
            float4 v = *(const float4*)(A + (size_t)(bm + m) * 512 + kk + kq);
            As[(kq + 0) * (P1_BM + 4) + m] = v.x;
            As[(kq + 1) * (P1_BM + 4) + m] = v.y;
            As[(kq + 2) * (P1_BM + 4) + m] = v.z;
            As[(kq + 3) * (P1_BM + 4) + m] = v.w;
        }
        // B tile 16x256 (1024 float4 slots, 4 per thread)
#pragma unroll
        for (int i = 0; i < 4; i++) {
            int s = tid + i * 256;
            int k = s >> 6;
            int n4 = (s & 63) << 2;
            float4 v = *(const float4*)(W + (size_t)(kk + k) * 1536 + bn + n4);
            *(float4*)(Bs + k * P1_BN + n4) = v;
        }
        __syncthreads();

#pragma unroll
        for (int k = 0; k < P1_BK; k++) {
            float4 a0 = *(const float4*)(As + k * (P1_BM + 4) + ty * 8);
            float4 a1 = *(const float4*)(As + k * (P1_BM + 4) + ty * 8 + 4);
            ull bp[8];
#pragma unroll
            for (int g = 0; g < 4; g++) {
                float4 b4 = *(const float4*)(Bs + k * P1_BN + tx * 4 + 64 * g);
                f4_to_u2(b4, bp[2 * g], bp[2 * g + 1]);
            }
            float am[8] = {a0.x, a0.y, a0.z, a0.w, a1.x, a1.y, a1.z, a1.w};
#pragma unroll
            for (int m = 0; m < 8; m++) {
                ull as = splat2(am[m]);
#pragma unroll
                for (int g = 0; g < 8; g++) fma2(acc[m][g], as, bp[g]);
            }
        }
        __syncthreads();
    }

    float4 bi[4];
#pragma unroll
    for (int g = 0; g < 4; g++)
        bi[g] = *(const float4*)(bias + bn + tx * 4 + 64 * g);
#pragma unroll
    for (int m = 0; m < 8; m++) {
        float* crow = C + (size_t)(bm + ty * 8 + m) * 1536;
#pragma unroll
        for (int g = 0; g < 4; g++) {
            float2 p0 = unpk(acc[m][2 * g]);
            float2 p1 = unpk(acc[m][2 * g + 1]);
            float4 o;
            o.x = p0.x + bi[g].x; o.y = p0.y + bi[g].y;
            o.z = p1.x + bi[g].z; o.w = p1.y + bi[g].w;
            *(float4*)(crow + bn + tx * 4 + 64 * g) = o;
        }
    }
}

// ============================================================================
// Phase 2: GRU recurrence, 128 CTAs = 8 batch-groups x 16 unit-groups.
//   CTA = (bg: 8 batches, ug: 32 units). R slice lives in REGISTERS
//   (96 f32x2/thread, loaded once). Per-bg monotonic-counter barrier (16 CTAs).
//   Thread roles: GEMM (warp=k-chunk kc, lane=unit uu);
//                 epilogue (warp=batch be, lane=unit uu).
// ============================================================================
#define NB2 128

__global__ void __launch_bounds__(256, 1) gru_seq_kernel(
    const float* __restrict__ xw,    // [65536, 1536]  (b*1024+t major)
    const float* __restrict__ rk,    // [512, 1536]
    const float* __restrict__ bias,  // [2, 1536] (row 1 = b_rec)
    float* __restrict__ out,         // [64, 1024, 512]
    float* __restrict__ h0buf,
    float* __restrict__ h1buf,
    unsigned* __restrict__ ctr)
{
    __shared__ float hs[8 * 512];        // 16 KB: h for this bg's 8 batches
    __shared__ float red[256 * 25];      // 25.6 KB: kc-partials (25 = pad, coprime 32)

    const int tid = threadIdx.x;
    const int bgid = blockIdx.x >> 4;    // 0..7
    const int ugid = blockIdx.x & 15;    // 0..15
    const int u0 = ugid * 32;
    const int b0 = bgid * 8;

    const int w  = tid >> 5;             // warp: GEMM k-chunk kc / epilogue batch be
    const int uu = tid & 31;             // unit within group

    // ---- load R slice into registers: unit u0+uu, k in [w*64, w*64+64) ----
    ull Rz[32], Rr[32], Rh[32];
    {
        const float* rbase = rk + u0 + uu;
#pragma unroll
        for (int i = 0; i < 32; i++) {
            int k = w * 64 + 2 * i;
            const float* r0 = rbase + (size_t)k * 1536;
            const float* r1 = r0 + 1536;
            Rz[i] = pack2(r0[0],    r1[0]);
            Rr[i] = pack2(r0[512],  r1[512]);
            Rh[i] = pack2(r0[1024], r1[1024]);
        }
    }
    const float bz  = bias[1536 + u0 + uu];
    const float brr = bias[1536 + 512 + u0 + uu];
    const float bh  = bias[1536 + 1024 + u0 + uu];

    const int bglob = b0 + w;                                 // epilogue batch
    const float* xwp = xw + (size_t)bglob * 1024 * 1536 + u0 + uu;
    float* outp = out + (size_t)bglob * 524288 + u0 + uu;
    unsigned* myctr = ctr + bgid * 32;

    for (int t = 0; t < 1024; t++) {
        const float* hin  = (t & 1) ? h1buf : h0buf;
        float*       hout = (t & 1) ? h0buf : h1buf;

        // prefetch gate inputs for this step (independent of h)
        const float* xr_ = xwp + (size_t)t * 1536;
        float xz = __ldg(xr_);
        float xr = __ldg(xr_ + 512);
        float xh = __ldg(xr_ + 1024);

        // ---- wait for h_t from the 16 CTAs of this batch-group ----
        if (t > 0) {
            if (tid == 0) {
                unsigned target = (unsigned)(16 * t);
                unsigned v;
                do {
                    asm volatile("ld.acquire.gpu.global.u32 %0, [%1];"
                                 : "=r"(v) : "l"(myctr) : "memory");
                } while (v < target);
            }
            __syncthreads();
        }

        // ---- stage h for this bg: 16 KB, 4 float4 per thread ----
        const float4* hsrc = (const float4*)(hin + b0 * 512);
#pragma unroll
        for (int i = 0; i < 4; i++) {
            int idx = tid + i * 256;
            ((float4*)hs)[idx] = __ldcg(hsrc + idx);
        }
        __syncthreads();

        // ---- GEMM partials: warp w handles k-chunk [w*64, w*64+64) ----
#pragma unroll 1
        for (int b = 0; b < 8; b++) {
            ull az = 0ull, ar = 0ull, ah = 0ull;
            const float4* hp = (const float4*)(hs + b * 512 + w * 64);
#pragma unroll
            for (int q = 0; q < 16; q++) {
                float4 h4 = hp[q];                 // broadcast across warp
                ull h01, h23;
                f4_to_u2(h4, h01, h23);
                fma2(az, h01, Rz[2 * q]); fma2(az, h23, Rz[2 * q + 1]);
                fma2(ar, h01, Rr[2 * q]); fma2(ar, h23, Rr[2 * q + 1]);
                fma2(ah, h01, Rh[2 * q]); fma2(ah, h23, Rh[2 * q + 1]);
            }
            float2 pz = unpk(az), pr = unpk(ar), ph = unpk(ah);
            float* rb = red + (b * 32 + uu) * 25 + w * 3;
            rb[0] = pz.x + pz.y;
            rb[1] = pr.x + pr.y;
            rb[2] = ph.x + ph.y;
        }
        __syncthreads();

        // ---- gates: thread = (batch w, unit uu) ----
        float rz = bz, rr = brr, rh = bh;
        const float* rb = red + (w * 32 + uu) * 25;
#pragma unroll
        for (int s = 0; s < 8; s++) {
            rz += rb[s * 3 + 0];
            rr += rb[s * 3 + 1];
            rh += rb[s * 3 + 2];
        }
        float hprev = hs[w * 512 + u0 + uu];
        float z  = sigf(xz + rz);
        float r  = sigf(xr + rr);
        float hh = tanh_acc(xh + r * rh);
        float hn = z * hprev + (1.0f - z) * hh;

        __stcg(hout + bglob * 512 + u0 + uu, hn);
        __threadfence();
        __syncthreads();
        if (tid == 0) atomicAdd(myctr, 1u);       // release: fence precedes

        // out write off the critical path (others are polling now)
        outp[(size_t)t * 512] = hn;
    }
}

// ============================================================================
extern "C" void kernel_launch(void* const* d_in, const int* in_sizes, int n_in,
                              void* d_out, int out_size) {
    const float* x    = (const float*)d_in[0];   // [64,1024,512]
    const float* W    = (const float*)d_in[1];   // [512,1536]
    const float* R    = (const float*)d_in[2];   // [512,1536]
    const float* bias = (const float*)d_in[3];   // [2,1536]
    float* out = (float*)d_out;

    float *xw_ptr, *h0_ptr, *h1_ptr;
    unsigned* ctr_ptr;
    cudaGetSymbolAddress((void**)&xw_ptr, g_xw);
    cudaGetSymbolAddress((void**)&h0_ptr, g_h0);
    cudaGetSymbolAddress((void**)&h1_ptr, g_h1);
    cudaGetSymbolAddress((void**)&ctr_ptr, g_ctr);

    cudaMemsetAsync(h0_ptr, 0, 64 * 512 * sizeof(float));
    cudaMemsetAsync(ctr_ptr, 0, 8 * 32 * sizeof(unsigned));

    dim3 g1(1536 / P1_BN, 65536 / P1_BM);
    gemm_xw_kernel<<<g1, 256>>>(x, W, bias, xw_ptr);

    gru_seq_kernel<<<NB2, 256>>>(xw_ptr, R, bias, out, h0_ptr, h1_ptr, ctr_ptr);
}